// round 5
// baseline (speedup 1.0000x reference)
#include <cuda_runtime.h>
#include <math.h>
#include <stdint.h>

#define N_CLASSES   1000
#define L4          250         // label row in float4s
#define EMBED       1024
#define THREADS     256
#define WARPS       8
#define GRID        148         // persistent: 1 CTA per SM
#define LAB_BYTES   4000
#define FEA_BYTES   4096
#define TX_BYTES    (LAB_BYTES + FEA_BYTES)     // 8096
#define STAGE_BYTES 8192        // labels [0,4096) (4000 used), features [4096,8192)
#define WARP_SMEM   (2 * STAGE_BYTES)
#define SMEM_DATA   (WARPS * WARP_SMEM)         // 131072
#define SMEM_TOTAL  (SMEM_DATA + WARPS * 2 * 8) // + mbarriers

__global__ void zero_out_kernel(float* out) { out[0] = 0.0f; }

__device__ __forceinline__ uint32_t smem_u32(const void* p) {
    uint32_t a;
    asm("{ .reg .u64 t; cvta.to.shared.u64 t, %1; cvt.u32.u64 %0, t; }"
        : "=r"(a) : "l"(p));
    return a;
}

__device__ __forceinline__ void mbar_init(uint32_t bar, uint32_t cnt) {
    asm volatile("mbarrier.init.shared.b64 [%0], %1;" :: "r"(bar), "r"(cnt) : "memory");
}

__device__ __forceinline__ void mbar_expect_tx(uint32_t bar, uint32_t bytes) {
    asm volatile("mbarrier.arrive.expect_tx.shared.b64 _, [%0], %1;"
                 :: "r"(bar), "r"(bytes) : "memory");
}

__device__ __forceinline__ void mbar_wait(uint32_t bar, uint32_t parity) {
    uint32_t done;
    asm volatile(
        "{\n\t.reg .pred p;\n\t"
        "mbarrier.try_wait.parity.acquire.cta.shared::cta.b64 p, [%1], %2;\n\t"
        "selp.b32 %0, 1, 0, p;\n\t}"
        : "=r"(done) : "r"(bar), "r"(parity) : "memory");
    if (!done) {
        asm volatile(
            "{\n\t.reg .pred P1;\n\t"
            "W_%=:\n\t"
            "mbarrier.try_wait.parity.acquire.cta.shared::cta.b64 P1, [%0], %1, 0x989680;\n\t"
            "@P1 bra.uni D_%=;\n\t"
            "bra.uni W_%=;\n\t"
            "D_%=:\n\t}"
            :: "r"(bar), "r"(parity) : "memory");
    }
}

__device__ __forceinline__ void bulk_copy(uint32_t dst, const void* src,
                                          uint32_t bytes, uint32_t bar) {
    asm volatile(
        "cp.async.bulk.shared::cluster.global.mbarrier::complete_tx::bytes "
        "[%0], [%1], %2, [%3];"
        :: "r"(dst), "l"(src), "r"(bytes), "r"(bar) : "memory");
}

__global__ void __launch_bounds__(THREADS, 1)
angular_loss_kernel(const float* __restrict__ features,
                    const float* __restrict__ labels,
                    const float* __restrict__ mean_class,
                    float* __restrict__ out,
                    int N)
{
    extern __shared__ char smem[];
    const int warp = threadIdx.x >> 5;
    const int lane = threadIdx.x & 31;

    char* my_base = smem + warp * WARP_SMEM;
    uint32_t bar_u32[2];
    bar_u32[0] = smem_u32(smem + SMEM_DATA + (warp * 2 + 0) * 8);
    bar_u32[1] = smem_u32(smem + SMEM_DATA + (warp * 2 + 1) * 8);
    uint32_t lab_u32[2], fea_u32[2];
    lab_u32[0] = smem_u32(my_base);
    lab_u32[1] = smem_u32(my_base + STAGE_BYTES);
    fea_u32[0] = lab_u32[0] + FEA_BYTES;   // features slot offset 4096
    fea_u32[1] = lab_u32[1] + FEA_BYTES;

    // init: barriers + zero the 96B label padding (bytes 4000..4095, both stages)
    if (lane == 0) {
        mbar_init(bar_u32[0], 1);
        mbar_init(bar_u32[1], 1);
    }
    if (lane < 24) {
        *(float*)(my_base + LAB_BYTES + lane * 4)               = 0.0f;
        *(float*)(my_base + STAGE_BYTES + LAB_BYTES + lane * 4) = 0.0f;
    }
    asm volatile("fence.proxy.async.shared::cta;" ::: "memory");
    __syncwarp();

    const int stride = GRID * WARPS;                  // total warps
    int r  = blockIdx.x * WARPS + warp;
    int s  = 0;
    int ph0 = 0, ph1 = 0;
    float acc = 0.0f;

    // prologue: issue row r into stage 0
    if (r < N && lane == 0) {
        mbar_expect_tx(bar_u32[0], TX_BYTES);
        bulk_copy(lab_u32[0], labels   + (size_t)r * N_CLASSES, LAB_BYTES, bar_u32[0]);
        bulk_copy(fea_u32[0], features + (size_t)r * EMBED,     FEA_BYTES, bar_u32[0]);
    }

    while (r < N) {
        const int rn = r + stride;
        const int sn = s ^ 1;
        // issue next row while current is consumed (engine-driven prefetch)
        if (rn < N && lane == 0) {
            mbar_expect_tx(bar_u32[sn], TX_BYTES);
            bulk_copy(lab_u32[sn], labels   + (size_t)rn * N_CLASSES, LAB_BYTES, bar_u32[sn]);
            bulk_copy(fea_u32[sn], features + (size_t)rn * EMBED,     FEA_BYTES, bar_u32[sn]);
        }

        // wait for current stage
        if (s == 0) { mbar_wait(bar_u32[0], ph0); ph0 ^= 1; }
        else        { mbar_wait(bar_u32[1], ph1); ph1 ^= 1; }

        const float4* lsm = (const float4*)(my_base + s * STAGE_BYTES);
        const float4* fsm = (const float4*)(my_base + s * STAGE_BYTES + FEA_BYTES);

        // resolve one-hot (c, v): padding floats [250,256) are zero
        int   c_loc = -1;
        float v_loc = 0.0f;
        #pragma unroll
        for (int k = 0; k < 8; k++) {
            const float4 lv = lsm[k * 32 + lane];
            const int base = (k * 32 + lane) * 4;
            if (lv.x != 0.0f) { c_loc = base + 0; v_loc = lv.x; }
            if (lv.y != 0.0f) { c_loc = base + 1; v_loc = lv.y; }
            if (lv.z != 0.0f) { c_loc = base + 2; v_loc = lv.z; }
            if (lv.w != 0.0f) { c_loc = base + 3; v_loc = lv.w; }
        }
        const unsigned found = __ballot_sync(0xFFFFFFFFu, c_loc >= 0);
        const int src = found ? (__ffs(found) - 1) : 0;
        int   c = __shfl_sync(0xFFFFFFFFu, c_loc, src);
        float v = __shfl_sync(0xFFFFFFFFu, v_loc, src);
        if (c < 0) { c = 0; v = 0.0f; }

        // issue L2-hot mean_class gather, then overlap with smem math
        const float4* mrow = (const float4*)(mean_class + (size_t)c * EMBED);
        float4 mv[8];
        #pragma unroll
        for (int k = 0; k < 8; k++) mv[k] = __ldg(&mrow[k * 32 + lane]);

        float ff = 0.0f, pp = 0.0f, fp = 0.0f;
        #pragma unroll
        for (int k = 0; k < 8; k++) {
            const float4 f = fsm[k * 32 + lane];
            const float4 m = mv[k];
            ff += f.x*f.x + f.y*f.y + f.z*f.z + f.w*f.w;
            pp += m.x*m.x + m.y*m.y + m.z*m.z + m.w*m.w;
            fp += f.x*m.x + f.y*m.y + f.z*m.z + f.w*m.w;
        }
        #pragma unroll
        for (int off = 16; off > 0; off >>= 1) {
            ff += __shfl_xor_sync(0xFFFFFFFFu, ff, off);
            pp += __shfl_xor_sync(0xFFFFFFFFu, pp, off);
            fp += __shfl_xor_sync(0xFFFFFFFFu, fp, off);
        }

        const float eps = 1e-12f;
        const float nf   = fmaxf(sqrtf(ff), eps);
        const float np   = fmaxf(fabsf(v) * sqrtf(pp), eps);
        acc += 1.0f - (v * fp) / (nf * np);

        // all lanes done reading stage s before it can be re-targeted next iter
        __syncwarp();
        s = sn;
        r = rn;
    }

    if (lane == 0 && acc != 0.0f)
        atomicAdd(out, acc / (float)N);
    else if (lane == 0) {
        // still contribute exact zero path cheaply (keeps determinism trivial)
        atomicAdd(out, acc / (float)N);
    }
}

extern "C" void kernel_launch(void* const* d_in, const int* in_sizes, int n_in,
                              void* d_out, int out_size)
{
    const float* features   = (const float*)d_in[0];
    const float* labels     = (const float*)d_in[1];
    const float* mean_class = (const float*)d_in[2];
    float* out = (float*)d_out;

    const int N = in_sizes[0] / EMBED;   // 32768

    cudaFuncSetAttribute(angular_loss_kernel,
                         cudaFuncAttributeMaxDynamicSharedMemorySize, SMEM_TOTAL);

    zero_out_kernel<<<1, 1>>>(out);
    angular_loss_kernel<<<GRID, THREADS, SMEM_TOTAL>>>(
        features, labels, mean_class, out, N);
}

// round 6
// speedup vs baseline: 1.1011x; 1.1011x over previous
#include <cuda_runtime.h>
#include <math.h>

#define N_CLASSES 1000
#define L4        250          // label row in float4s (1000/4)
#define EMBED     1024
#define THREADS   256
#define WPB       8            // warps (rows) per block
#define GRID      4096         // 32768 / WPB

__device__ float        g_acc;     // zero-initialized at module load
__device__ unsigned int g_count;   // reset to 0 by last block each run

__global__ void __launch_bounds__(THREADS, 4)
angular_loss_kernel(const float* __restrict__ features,
                    const float* __restrict__ labels,
                    const float* __restrict__ mean_class,
                    float* __restrict__ out,
                    int N)
{
    const int warp = threadIdx.x >> 5;
    const int lane = threadIdx.x & 31;
    const int row  = blockIdx.x * WPB + warp;

    __shared__ float s_part[WPB];

    const float4* lrow = reinterpret_cast<const float4*>(
        labels + (size_t)row * N_CLASSES);
    const float4* frow = reinterpret_cast<const float4*>(
        features + (size_t)row * EMBED);

    // ---- front-batch both DRAM streams, interleaved ----
    float4 lv[8], fv[8];
    #pragma unroll
    for (int k = 0; k < 8; k++) {
        const int idx = k * 32 + lane;
        lv[k] = (idx < L4) ? __ldcs(&lrow[idx]) : make_float4(0.f, 0.f, 0.f, 0.f);
        fv[k] = __ldcs(&frow[idx]);
    }

    // ---- resolve the one-hot (c, v) for this row ----
    int   c_loc = -1;
    float v_loc = 0.0f;
    #pragma unroll
    for (int k = 0; k < 8; k++) {
        const int base = (k * 32 + lane) * 4;
        if (lv[k].x != 0.0f) { c_loc = base + 0; v_loc = lv[k].x; }
        if (lv[k].y != 0.0f) { c_loc = base + 1; v_loc = lv[k].y; }
        if (lv[k].z != 0.0f) { c_loc = base + 2; v_loc = lv[k].z; }
        if (lv[k].w != 0.0f) { c_loc = base + 3; v_loc = lv[k].w; }
    }
    const unsigned found = __ballot_sync(0xFFFFFFFFu, c_loc >= 0);
    const int src = found ? (__ffs(found) - 1) : 0;
    int   c = __shfl_sync(0xFFFFFFFFu, c_loc, src);
    float v = __shfl_sync(0xFFFFFFFFu, v_loc, src);
    if (c < 0) { c = 0; v = 0.0f; }

    // ---- gather mean_class[c] (L2-hot) and compute ff, pp, fp ----
    const float4* mrow = reinterpret_cast<const float4*>(
        mean_class + (size_t)c * EMBED);
    float4 mv[8];
    #pragma unroll
    for (int k = 0; k < 8; k++) mv[k] = __ldg(&mrow[k * 32 + lane]);

    float ff = 0.0f, pp = 0.0f, fp = 0.0f;
    #pragma unroll
    for (int k = 0; k < 8; k++) {
        const float4 f = fv[k];
        const float4 m = mv[k];
        ff += f.x*f.x + f.y*f.y + f.z*f.z + f.w*f.w;
        pp += m.x*m.x + m.y*m.y + m.z*m.z + m.w*m.w;
        fp += f.x*m.x + f.y*m.y + f.z*m.z + f.w*m.w;
    }
    #pragma unroll
    for (int off = 16; off > 0; off >>= 1) {
        ff += __shfl_xor_sync(0xFFFFFFFFu, ff, off);
        pp += __shfl_xor_sync(0xFFFFFFFFu, pp, off);
        fp += __shfl_xor_sync(0xFFFFFFFFu, fp, off);
    }

    if (lane == 0) {
        const float eps = 1e-12f;
        const float nf   = fmaxf(sqrtf(ff), eps);
        const float np   = fmaxf(fabsf(v) * sqrtf(pp), eps);
        const float cosv = (v * fp) / (nf * np);
        s_part[warp] = 1.0f - cosv;
    }
    __syncthreads();

    // ---- block partial -> global accumulator; last block finishes ----
    if (threadIdx.x == 0) {
        float s = 0.0f;
        #pragma unroll
        for (int w = 0; w < WPB; w++) s += s_part[w];
        atomicAdd(&g_acc, s / (float)N);
        __threadfence();
        const unsigned ticket = atomicAdd(&g_count, 1u);
        if (ticket == (unsigned)(gridDim.x - 1)) {
            out[0] = g_acc;           // all prior adds visible via fence+ticket
            g_acc   = 0.0f;           // reset for next graph replay
            g_count = 0u;
        }
    }
}

extern "C" void kernel_launch(void* const* d_in, const int* in_sizes, int n_in,
                              void* d_out, int out_size)
{
    const float* features   = (const float*)d_in[0];
    const float* labels     = (const float*)d_in[1];
    const float* mean_class = (const float*)d_in[2];
    float* out = (float*)d_out;

    const int N = in_sizes[0] / EMBED;   // 32768

    angular_loss_kernel<<<GRID, THREADS>>>(
        features, labels, mean_class, out, N);
}